// round 4
// baseline (speedup 1.0000x reference)
#include <cuda_runtime.h>
#include <cuda_bf16.h>
#include <cstdint>

// Problem shape (fixed by the reference): B=4, L=4096, H=1024, F=4096
#define M_TOK  16384
#define H_DIM  1024
#define F_DIM  4096

// Compacted intermediate h = relu(x_gathered @ W1 + b1): dense rows [0, Mc)
__device__ float g_h[(size_t)M_TOK * F_DIM];
__device__ int   g_idx[M_TOK];   // g_idx[r] = source token index of compacted row r
__device__ int   g_Mc;           // number of real (non-padded) tokens

#define AS_STRIDE 36    // 32+4 pad: A-frag bank = (4g+tg) -> bijection, conflict-free
#define BS_STRIDE 132   // 128+4 pad: B-frag bank = (4tg+g) -> bijection, conflict-free
#define AS_WORDS  (128 * AS_STRIDE)
#define BS_WORDS  (32 * BS_STRIDE)
#define SMEM_BYTES ((2 * (AS_WORDS + BS_WORDS)) * 4)   // 70656 B

// ---------------------------------------------------------------------------
// Aux kernel 1: zero the output (covers padded rows + harness 0xAA poison)
__global__ void zero_out_kernel(float4* out, int n4) {
    int i = blockIdx.x * blockDim.x + threadIdx.x;
    if (i < n4) out[i] = make_float4(0.f, 0.f, 0.f, 0.f);
}

// ---------------------------------------------------------------------------
// Aux kernel 2: order-preserving compaction of non-padded token indices.
// Single block, 1024 threads, 16 tokens/thread; warp-shuffle + smem scan.
__global__ __launch_bounds__(1024) void compact_kernel(const int* __restrict__ padding) {
    __shared__ int warp_tot[32];
    const int t    = threadIdx.x;
    const int lane = t & 31;
    const int w    = t >> 5;

    int flags = 0, cnt = 0;
    const int base = t * 16;
#pragma unroll
    for (int i = 0; i < 16; ++i) {
        int f = (padding[base + i] == 0);
        flags |= f << i;
        cnt += f;
    }

    // inclusive warp scan of cnt
    int inc = cnt;
#pragma unroll
    for (int d = 1; d < 32; d <<= 1) {
        int v = __shfl_up_sync(0xFFFFFFFFu, inc, d);
        if (lane >= d) inc += v;
    }
    if (lane == 31) warp_tot[w] = inc;
    __syncthreads();

    if (w == 0) {
        int v = warp_tot[lane];
        int s = v;
#pragma unroll
        for (int d = 1; d < 32; d <<= 1) {
            int u = __shfl_up_sync(0xFFFFFFFFu, s, d);
            if (lane >= d) s += u;
        }
        warp_tot[lane] = s - v;   // exclusive warp prefix
        if (lane == 31) g_Mc = s; // total count
    }
    __syncthreads();

    int off = warp_tot[w] + (inc - cnt);   // exclusive prefix for this thread
#pragma unroll
    for (int i = 0; i < 16; ++i)
        if ((flags >> i) & 1) g_idx[off++] = base + i;
}

// ---------------------------------------------------------------------------
// tf32 helpers
__device__ __forceinline__ uint32_t f2tf32(float x) {
    uint32_t r;
    asm("cvt.rna.tf32.f32 %0, %1;" : "=r"(r) : "f"(x));
    return r;
}
__device__ __forceinline__ void mma_tf32(float* c, const uint32_t* a, const uint32_t* b) {
    asm volatile(
        "mma.sync.aligned.m16n8k8.row.col.f32.tf32.tf32.f32 "
        "{%0,%1,%2,%3}, {%4,%5,%6,%7}, {%8,%9}, {%0,%1,%2,%3};"
        : "+f"(c[0]), "+f"(c[1]), "+f"(c[2]), "+f"(c[3])
        : "r"(a[0]), "r"(a[1]), "r"(a[2]), "r"(a[3]), "r"(b[0]), "r"(b[1]));
}

// ---------------------------------------------------------------------------
// Fused compacted GEMM.
//   MODE 0: A = x (rows gathered via g_idx), C = g_h (dense), epilogue relu
//   MODE 1: A = g_h (dense),  C = out (rows scattered via g_idx), no mask
// 128x128x32 tile, 256 threads, 8 warps (2m x 4n), warp tile 64x32,
// double-buffered smem (one barrier per k-tile). Only rows < Mc computed/stored.
template <int MODE>
__global__ __launch_bounds__(256)
void ffn_mma_kernel(const float* __restrict__ A,
                    const float* __restrict__ Bw,
                    const float* __restrict__ bias,
                    float*       __restrict__ C,
                    int N, int K)
{
    const int Mc = g_Mc;
    const int bm = blockIdx.y * 128;
    if (bm >= Mc) return;                 // whole CTA: dead tile

    extern __shared__ uint32_t smem[];
    uint32_t* AsBuf = smem;
    uint32_t* BsBuf = smem + 2 * AS_WORDS;

    const int tid  = threadIdx.x;
    const int wid  = tid >> 5;
    const int lane = tid & 31;
    const int g    = lane >> 2;
    const int tg   = lane & 3;
    const int warp_m = wid & 1;
    const int warp_n = wid >> 1;
    const int bn = blockIdx.x * 128;

    const float* Aeff = (MODE == 1) ? (const float*)g_h : A;

    // ---- global load mapping (per tile: A 128x32, B 32x128, 4 float4/thread)
    const int a_row0 = tid >> 3;          // + 32*i
    const int a_kq   = (tid & 7) * 4;
    const int b_k0   = tid >> 5;          // + 8*i
    const int b_nq   = (tid & 31) * 4;

    // Resolve the 4 A source rows once (gather for MODE 0, dense otherwise).
    size_t a_rowoff[4];
#pragma unroll
    for (int i = 0; i < 4; ++i) {
        int r = bm + a_row0 + 32 * i;
        int src;
        if (MODE == 0) src = (r < Mc) ? g_idx[r] : 0;   // clamp: garbage ok, never stored
        else           src = (r < Mc) ? r : 0;
        a_rowoff[i] = (size_t)src * K + a_kq;
    }
    const float* Bptr = Bw + (size_t)b_k0 * N + bn + b_nq;

    float acc[4][4][4];
#pragma unroll
    for (int mt = 0; mt < 4; ++mt)
#pragma unroll
        for (int nt = 0; nt < 4; ++nt)
#pragma unroll
            for (int i = 0; i < 4; ++i) acc[mt][nt][i] = 0.f;

    const int KT = K / 32;
    float4 ra[4], rb[4];

    // ---- prologue: tile 0 -> buffer 0
#pragma unroll
    for (int i = 0; i < 4; ++i) ra[i] = *(const float4*)(Aeff + a_rowoff[i]);
#pragma unroll
    for (int i = 0; i < 4; ++i) rb[i] = *(const float4*)(Bptr + (size_t)(8 * i) * N);

#pragma unroll
    for (int i = 0; i < 4; ++i) {
        uint4 u;
        u.x = f2tf32(ra[i].x); u.y = f2tf32(ra[i].y);
        u.z = f2tf32(ra[i].z); u.w = f2tf32(ra[i].w);
        *(uint4*)&AsBuf[(a_row0 + 32 * i) * AS_STRIDE + a_kq] = u;
    }
#pragma unroll
    for (int i = 0; i < 4; ++i) {
        uint4 u;
        u.x = f2tf32(rb[i].x); u.y = f2tf32(rb[i].y);
        u.z = f2tf32(rb[i].z); u.w = f2tf32(rb[i].w);
        *(uint4*)&BsBuf[(b_k0 + 8 * i) * BS_STRIDE + b_nq] = u;
    }
    __syncthreads();

    for (int t = 0; t < KT; ++t) {
        const uint32_t* As = AsBuf + (t & 1) * AS_WORDS;
        const uint32_t* Bs = BsBuf + (t & 1) * BS_WORDS;

        const bool have_next = (t + 1 < KT);
        if (have_next) {
            const int k0 = (t + 1) * 32;
#pragma unroll
            for (int i = 0; i < 4; ++i)
                ra[i] = *(const float4*)(Aeff + a_rowoff[i] + k0);
#pragma unroll
            for (int i = 0; i < 4; ++i)
                rb[i] = *(const float4*)(Bptr + (size_t)(k0 + 8 * i) * N);
        }

#pragma unroll
        for (int ks = 0; ks < 4; ++ks) {
            const int k = ks * 8;
            uint32_t af[4][4];
#pragma unroll
            for (int mt = 0; mt < 4; ++mt) {
                const int m0 = warp_m * 64 + mt * 16;
                af[mt][0] = As[(m0 + g)     * AS_STRIDE + k + tg];
                af[mt][1] = As[(m0 + g + 8) * AS_STRIDE + k + tg];
                af[mt][2] = As[(m0 + g)     * AS_STRIDE + k + tg + 4];
                af[mt][3] = As[(m0 + g + 8) * AS_STRIDE + k + tg + 4];
            }
            uint32_t bf[4][2];
#pragma unroll
            for (int nt = 0; nt < 4; ++nt) {
                const int n0 = warp_n * 32 + nt * 8 + g;
                bf[nt][0] = Bs[(k + tg)     * BS_STRIDE + n0];
                bf[nt][1] = Bs[(k + tg + 4) * BS_STRIDE + n0];
            }
#pragma unroll
            for (int mt = 0; mt < 4; ++mt)
#pragma unroll
                for (int nt = 0; nt < 4; ++nt)
                    mma_tf32(acc[mt][nt], af[mt], bf[nt]);
        }

        if (have_next) {
            uint32_t* Asn = AsBuf + ((t + 1) & 1) * AS_WORDS;
            uint32_t* Bsn = BsBuf + ((t + 1) & 1) * BS_WORDS;
#pragma unroll
            for (int i = 0; i < 4; ++i) {
                uint4 u;
                u.x = f2tf32(ra[i].x); u.y = f2tf32(ra[i].y);
                u.z = f2tf32(ra[i].z); u.w = f2tf32(ra[i].w);
                *(uint4*)&Asn[(a_row0 + 32 * i) * AS_STRIDE + a_kq] = u;
            }
#pragma unroll
            for (int i = 0; i < 4; ++i) {
                uint4 u;
                u.x = f2tf32(rb[i].x); u.y = f2tf32(rb[i].y);
                u.z = f2tf32(rb[i].z); u.w = f2tf32(rb[i].w);
                *(uint4*)&Bsn[(b_k0 + 8 * i) * BS_STRIDE + b_nq] = u;
            }
            __syncthreads();
        }
    }

    // ---- epilogue ----
#pragma unroll
    for (int mt = 0; mt < 4; ++mt) {
        const int r0 = bm + warp_m * 64 + mt * 16 + g;
        const int r1 = r0 + 8;

        float* Crow0 = nullptr;
        float* Crow1 = nullptr;
        if (r0 < Mc)
            Crow0 = (MODE == 0) ? (float*)g_h + (size_t)r0 * N
                                : C + (size_t)g_idx[r0] * N;
        if (r1 < Mc)
            Crow1 = (MODE == 0) ? (float*)g_h + (size_t)r1 * N
                                : C + (size_t)g_idx[r1] * N;

#pragma unroll
        for (int nt = 0; nt < 4; ++nt) {
            const int c = bn + warp_n * 32 + nt * 8 + tg * 2;
            const float2 bb = *(const float2*)&bias[c];

            float2 v0, v1;
            v0.x = acc[mt][nt][0] + bb.x;
            v0.y = acc[mt][nt][1] + bb.y;
            v1.x = acc[mt][nt][2] + bb.x;
            v1.y = acc[mt][nt][3] + bb.y;

            if (MODE == 0) {
                v0.x = fmaxf(v0.x, 0.f); v0.y = fmaxf(v0.y, 0.f);
                v1.x = fmaxf(v1.x, 0.f); v1.y = fmaxf(v1.y, 0.f);
            }
            if (Crow0) *(float2*)&Crow0[c] = v0;
            if (Crow1) *(float2*)&Crow1[c] = v1;
        }
    }
}

extern "C" void kernel_launch(void* const* d_in, const int* in_sizes, int n_in,
                              void* d_out, int out_size)
{
    const float* x       = (const float*)d_in[0];  // [4,4096,1024]
    const int*   padding = (const int*)  d_in[1];  // [4,4096]
    const float* W1      = (const float*)d_in[2];  // [1024,4096]
    const float* b1      = (const float*)d_in[3];  // [4096]
    const float* W2      = (const float*)d_in[4];  // [4096,1024]
    const float* b2      = (const float*)d_in[5];  // [1024]
    float*       out     = (float*)d_out;          // [4,4096,1024]

    cudaFuncSetAttribute(ffn_mma_kernel<0>,
                         cudaFuncAttributeMaxDynamicSharedMemorySize, SMEM_BYTES);
    cudaFuncSetAttribute(ffn_mma_kernel<1>,
                         cudaFuncAttributeMaxDynamicSharedMemorySize, SMEM_BYTES);

    // 1) zero out (padded rows stay zero; clears 0xAA poison)
    const int n4 = M_TOK * H_DIM / 4;
    zero_out_kernel<<<(n4 + 255) / 256, 256>>>((float4*)out, n4);

    // 2) compact non-padded token indices -> g_idx / g_Mc
    compact_kernel<<<1, 1024>>>(padding);

    dim3 block(256);

    // 3) GEMM1 (gathered): h_c = relu(x[idx] @ W1 + b1)  [Mc x 4096], K=1024
    dim3 grid1(F_DIM / 128, M_TOK / 128);   // worst-case grid; dead tiles exit
    ffn_mma_kernel<0><<<grid1, block, SMEM_BYTES>>>(x, W1, b1, nullptr,
                                                    F_DIM, H_DIM);

    // 4) GEMM2 (scattered): out[idx] = h_c @ W2 + b2  [Mc x 1024], K=4096
    dim3 grid2(H_DIM / 128, M_TOK / 128);
    ffn_mma_kernel<1><<<grid2, block, SMEM_BYTES>>>(nullptr, W2, b2, out,
                                                    H_DIM, F_DIM);
}

// round 9
// speedup vs baseline: 1.2159x; 1.2159x over previous
#include <cuda_runtime.h>
#include <cuda_bf16.h>
#include <cstdint>

// Problem shape (fixed by the reference): B=4, L=4096, H=1024, F=4096
#define M_TOK  16384
#define H_DIM  1024
#define F_DIM  4096

// Compacted intermediate h (stored TF32-rounded): dense rows [0, Mc)
__device__ float g_h[(size_t)M_TOK * F_DIM];
// Pre-rounded (RNA tf32) weights
__device__ float g_w1[(size_t)H_DIM * F_DIM];
__device__ float g_w2[(size_t)F_DIM * H_DIM];
__device__ int   g_idx[M_TOK];
__device__ int   g_Mc;

#define AS_STRIDE 36    // 32+4 pad: A-frag bank = (4g+tg) -> bijection, conflict-free
#define BS_STRIDE 132   // 128+4 pad: B-frag bank = (4tg+g) -> bijection, conflict-free
#define AS_WORDS  (128 * AS_STRIDE)
#define BS_WORDS  (32 * BS_STRIDE)
#define SMEM_BYTES ((2 * (AS_WORDS + BS_WORDS)) * 4)   // 70656 B

// ---------------------------------------------------------------------------
__device__ __forceinline__ uint32_t f2tf32(float x) {
    uint32_t r;
    asm("cvt.rna.tf32.f32 %0, %1;" : "=r"(r) : "f"(x));
    return r;
}

// Aux 1: zero output (padded rows + 0xAA poison)
__global__ void zero_out_kernel(float4* out, int n4) {
    int i = blockIdx.x * blockDim.x + threadIdx.x;
    if (i < n4) out[i] = make_float4(0.f, 0.f, 0.f, 0.f);
}

// Aux 2: RNA-round both weight matrices into device globals (streaming).
__global__ void round_weights_kernel(const float4* __restrict__ w1,
                                     const float4* __restrict__ w2) {
    const int n1 = H_DIM * F_DIM / 4;
    const int n2 = F_DIM * H_DIM / 4;
    for (int i = blockIdx.x * blockDim.x + threadIdx.x; i < n1 + n2;
         i += gridDim.x * blockDim.x) {
        float4 v = (i < n1) ? w1[i] : w2[i - n1];
        uint4 u;
        u.x = f2tf32(v.x); u.y = f2tf32(v.y);
        u.z = f2tf32(v.z); u.w = f2tf32(v.w);
        if (i < n1) ((uint4*)g_w1)[i] = u;
        else        ((uint4*)g_w2)[i - n1] = u;
    }
}

// Aux 3: order-preserving compaction of non-padded token indices.
__global__ __launch_bounds__(1024) void compact_kernel(const int* __restrict__ padding) {
    __shared__ int warp_tot[32];
    const int t    = threadIdx.x;
    const int lane = t & 31;
    const int w    = t >> 5;

    int flags = 0, cnt = 0;
    const int base = t * 16;
#pragma unroll
    for (int i = 0; i < 16; ++i) {
        int f = (padding[base + i] == 0);
        flags |= f << i;
        cnt += f;
    }
    int inc = cnt;
#pragma unroll
    for (int d = 1; d < 32; d <<= 1) {
        int v = __shfl_up_sync(0xFFFFFFFFu, inc, d);
        if (lane >= d) inc += v;
    }
    if (lane == 31) warp_tot[w] = inc;
    __syncthreads();
    if (w == 0) {
        int v = warp_tot[lane];
        int s = v;
#pragma unroll
        for (int d = 1; d < 32; d <<= 1) {
            int u = __shfl_up_sync(0xFFFFFFFFu, s, d);
            if (lane >= d) s += u;
        }
        warp_tot[lane] = s - v;
        if (lane == 31) g_Mc = s;
    }
    __syncthreads();
    int off = warp_tot[w] + (inc - cnt);
#pragma unroll
    for (int i = 0; i < 16; ++i)
        if ((flags >> i) & 1) g_idx[off++] = base + i;
}

// ---------------------------------------------------------------------------
__device__ __forceinline__ void mma_tf32(float* c, const uint32_t* a, const uint32_t* b) {
    asm volatile(
        "mma.sync.aligned.m16n8k8.row.col.f32.tf32.tf32.f32 "
        "{%0,%1,%2,%3}, {%4,%5,%6,%7}, {%8,%9}, {%0,%1,%2,%3};"
        : "+f"(c[0]), "+f"(c[1]), "+f"(c[2]), "+f"(c[3])
        : "r"(a[0]), "r"(a[1]), "r"(a[2]), "r"(a[3]), "r"(b[0]), "r"(b[1]));
}
__device__ __forceinline__ void cp_async16(uint32_t smem_dst, const void* gsrc) {
    asm volatile("cp.async.cg.shared.global [%0], [%1], 16;" :: "r"(smem_dst), "l"(gsrc));
}
__device__ __forceinline__ void cp_commit() {
    asm volatile("cp.async.commit_group;");
}
__device__ __forceinline__ void cp_wait0() {
    asm volatile("cp.async.wait_group 0;" ::: "memory");
}

// ---------------------------------------------------------------------------
// Fused compacted GEMM. All smem-resident operands already tf32-rounded:
//   MODE 0: A = x (gathered, LDG+RNA+STS), B = g_w1 (cp.async),
//           C = g_h (stores tf32-rounded relu)
//   MODE 1: A = g_h (cp.async), B = g_w2 (cp.async), C = out (scatter rows)
// 128x128x32 tile, 256 threads, 8 warps (2m x 4n), warp tile 64x32,
// double-buffered, one barrier per k-tile, 2 CTAs/SM. Inner loop: LDS+MMA only.
template <int MODE>
__global__ __launch_bounds__(256, 2)
void ffn_mma_kernel(const float* __restrict__ A,
                    const float* __restrict__ bias,
                    float*       __restrict__ C,
                    int N, int K)
{
    const int Mc = g_Mc;
    const int bm = blockIdx.y * 128;
    if (bm >= Mc) return;

    extern __shared__ uint32_t smem[];
    uint32_t* AsBuf = smem;
    uint32_t* BsBuf = smem + 2 * AS_WORDS;

    const int tid  = threadIdx.x;
    const int wid  = tid >> 5;
    const int lane = tid & 31;
    const int g    = lane >> 2;
    const int tg   = lane & 3;
    const int warp_m = wid & 1;
    const int warp_n = wid >> 1;
    const int bn = blockIdx.x * 128;

    const float* Aeff = (MODE == 1) ? (const float*)g_h : A;
    const float* Bw   = (MODE == 0) ? (const float*)g_w1 : (const float*)g_w2;

    // ---- load mappings (per tile: A 128x32, B 32x128, 4x16B per thread each)
    const int a_row0 = tid >> 3;          // + 32*i
    const int a_kq   = (tid & 7) * 4;
    const int b_k0   = tid >> 5;          // + 8*i
    const int b_nq   = (tid & 31) * 4;

    size_t a_rowoff[4];
#pragma unroll
    for (int i = 0; i < 4; ++i) {
        int r = bm + a_row0 + 32 * i;
        int src;
        if (MODE == 0) src = (r < Mc) ? g_idx[r] : 0;   // clamp: never stored
        else           src = (r < Mc) ? r : 0;
        a_rowoff[i] = (size_t)src * K + a_kq;
    }
    const float* Bptr = Bw + (size_t)b_k0 * N + bn + b_nq;

    const uint32_t b_dst_base = (uint32_t)__cvta_generic_to_shared(BsBuf)
                              + (uint32_t)(b_k0 * BS_STRIDE + b_nq) * 4u;
    const uint32_t a_dst_base = (uint32_t)__cvta_generic_to_shared(AsBuf)
                              + (uint32_t)(a_row0 * AS_STRIDE + a_kq) * 4u;

    float acc[4][4][4];
#pragma unroll
    for (int mt = 0; mt < 4; ++mt)
#pragma unroll
        for (int nt = 0; nt < 4; ++nt)
#pragma unroll
            for (int i = 0; i < 4; ++i) acc[mt][nt][i] = 0.f;

    const int KT = K / 32;
    float4 ra[4];

    // ---- prologue: stage tile 0 into buffer 0
    if (MODE == 0) {
#pragma unroll
        for (int i = 0; i < 4; ++i) ra[i] = *(const float4*)(Aeff + a_rowoff[i]);
    } else {
#pragma unroll
        for (int i = 0; i < 4; ++i)
            cp_async16(a_dst_base + (uint32_t)(32 * i * AS_STRIDE) * 4u,
                       Aeff + a_rowoff[i]);
    }
#pragma unroll
    for (int i = 0; i < 4; ++i)
        cp_async16(b_dst_base + (uint32_t)(8 * i * BS_STRIDE) * 4u,
                   Bptr + (size_t)(8 * i) * N);
    cp_commit();

    if (MODE == 0) {
#pragma unroll
        for (int i = 0; i < 4; ++i) {
            uint4 u;
            u.x = f2tf32(ra[i].x); u.y = f2tf32(ra[i].y);
            u.z = f2tf32(ra[i].z); u.w = f2tf32(ra[i].w);
            *(uint4*)&AsBuf[(a_row0 + 32 * i) * AS_STRIDE + a_kq] = u;
        }
    }
    cp_wait0();
    __syncthreads();

    for (int t = 0; t < KT; ++t) {
        const uint32_t* As = AsBuf + (t & 1) * AS_WORDS;
        const uint32_t* Bs = BsBuf + (t & 1) * BS_WORDS;
        const uint32_t buf_next = ((t + 1) & 1);

        // ---- start async loads for tile t+1
        const bool have_next = (t + 1 < KT);
        if (have_next) {
            const int k0 = (t + 1) * 32;
            if (MODE == 0) {
#pragma unroll
                for (int i = 0; i < 4; ++i)
                    ra[i] = *(const float4*)(Aeff + a_rowoff[i] + k0);
            } else {
#pragma unroll
                for (int i = 0; i < 4; ++i)
                    cp_async16(a_dst_base + (buf_next * AS_WORDS
                               + (uint32_t)(32 * i * AS_STRIDE)) * 4u,
                               Aeff + a_rowoff[i] + k0);
            }
#pragma unroll
            for (int i = 0; i < 4; ++i)
                cp_async16(b_dst_base + (buf_next * BS_WORDS
                           + (uint32_t)(8 * i * BS_STRIDE)) * 4u,
                           Bptr + (size_t)(k0 + 8 * i) * N);
            cp_commit();
        }

        // ---- compute: 4 k-steps x (4 m x 4 n) mmas — pure LDS + MMA
#pragma unroll
        for (int ks = 0; ks < 4; ++ks) {
            const int k = ks * 8;
            uint32_t af[4][4];
#pragma unroll
            for (int mt = 0; mt < 4; ++mt) {
                const int m0 = warp_m * 64 + mt * 16;
                af[mt][0] = As[(m0 + g)     * AS_STRIDE + k + tg];
                af[mt][1] = As[(m0 + g + 8) * AS_STRIDE + k + tg];
                af[mt][2] = As[(m0 + g)     * AS_STRIDE + k + tg + 4];
                af[mt][3] = As[(m0 + g + 8) * AS_STRIDE + k + tg + 4];
            }
            uint32_t bf[4][2];
#pragma unroll
            for (int nt = 0; nt < 4; ++nt) {
                const int n0 = warp_n * 32 + nt * 8 + g;
                bf[nt][0] = Bs[(k + tg)     * BS_STRIDE + n0];
                bf[nt][1] = Bs[(k + tg + 4) * BS_STRIDE + n0];
            }
#pragma unroll
            for (int mt = 0; mt < 4; ++mt)
#pragma unroll
                for (int nt = 0; nt < 4; ++nt)
                    mma_tf32(acc[mt][nt], af[mt], bf[nt]);
        }

        // ---- stage next A (register path, MODE 0 only), seal tile
        if (have_next) {
            if (MODE == 0) {
                uint32_t* Asn = AsBuf + buf_next * AS_WORDS;
#pragma unroll
                for (int i = 0; i < 4; ++i) {
                    uint4 u;
                    u.x = f2tf32(ra[i].x); u.y = f2tf32(ra[i].y);
                    u.z = f2tf32(ra[i].z); u.w = f2tf32(ra[i].w);
                    *(uint4*)&Asn[(a_row0 + 32 * i) * AS_STRIDE + a_kq] = u;
                }
            }
            cp_wait0();
            __syncthreads();
        }
    }

    // ---- epilogue ----
#pragma unroll
    for (int mt = 0; mt < 4; ++mt) {
        const int r0 = bm + warp_m * 64 + mt * 16 + g;
        const int r1 = r0 + 8;

        float* Crow0 = nullptr;
        float* Crow1 = nullptr;
        if (r0 < Mc)
            Crow0 = (MODE == 0) ? (float*)g_h + (size_t)r0 * N
                                : C + (size_t)g_idx[r0] * N;
        if (r1 < Mc)
            Crow1 = (MODE == 0) ? (float*)g_h + (size_t)r1 * N
                                : C + (size_t)g_idx[r1] * N;

#pragma unroll
        for (int nt = 0; nt < 4; ++nt) {
            const int c = bn + warp_n * 32 + nt * 8 + tg * 2;
            const float2 bb = *(const float2*)&bias[c];

            float2 v0, v1;
            v0.x = acc[mt][nt][0] + bb.x;
            v0.y = acc[mt][nt][1] + bb.y;
            v1.x = acc[mt][nt][2] + bb.x;
            v1.y = acc[mt][nt][3] + bb.y;

            if (MODE == 0) {
                // relu + pre-round so GEMM2 consumes h with zero conversion
                v0.x = __uint_as_float(f2tf32(fmaxf(v0.x, 0.f)));
                v0.y = __uint_as_float(f2tf32(fmaxf(v0.y, 0.f)));
                v1.x = __uint_as_float(f2tf32(fmaxf(v1.x, 0.f)));
                v1.y = __uint_as_float(f2tf32(fmaxf(v1.y, 0.f)));
            }
            if (Crow0) *(float2*)&Crow0[c] = v0;
            if (Crow1) *(float2*)&Crow1[c] = v1;
        }
    }
}

extern "C" void kernel_launch(void* const* d_in, const int* in_sizes, int n_in,
                              void* d_out, int out_size)
{
    const float* x       = (const float*)d_in[0];  // [4,4096,1024]
    const int*   padding = (const int*)  d_in[1];  // [4,4096]
    const float* W1      = (const float*)d_in[2];  // [1024,4096]
    const float* b1      = (const float*)d_in[3];  // [4096]
    const float* W2      = (const float*)d_in[4];  // [4096,1024]
    const float* b2      = (const float*)d_in[5];  // [1024]
    float*       out     = (float*)d_out;          // [4,4096,1024]

    cudaFuncSetAttribute(ffn_mma_kernel<0>,
                         cudaFuncAttributeMaxDynamicSharedMemorySize, SMEM_BYTES);
    cudaFuncSetAttribute(ffn_mma_kernel<1>,
                         cudaFuncAttributeMaxDynamicSharedMemorySize, SMEM_BYTES);

    const int n4 = M_TOK * H_DIM / 4;
    zero_out_kernel<<<(n4 + 255) / 256, 256>>>((float4*)out, n4);
    round_weights_kernel<<<1184, 256>>>((const float4*)W1, (const float4*)W2);
    compact_kernel<<<1, 1024>>>(padding);

    dim3 block(256);

    // GEMM1 (gathered): h_c = tf32(relu(x[idx] @ W1 + b1))  [Mc x 4096], K=1024
    dim3 grid1(F_DIM / 128, M_TOK / 128);
    ffn_mma_kernel<0><<<grid1, block, SMEM_BYTES>>>(x, b1, nullptr, F_DIM, H_DIM);

    // GEMM2 (scattered): out[idx] = h_c @ W2 + b2  [Mc x 1024], K=4096
    dim3 grid2(H_DIM / 128, M_TOK / 128);
    ffn_mma_kernel<1><<<grid2, block, SMEM_BYTES>>>(nullptr, b2, out, H_DIM, F_DIM);
}

// round 12
// speedup vs baseline: 1.2634x; 1.0391x over previous
#include <cuda_runtime.h>
#include <cuda_bf16.h>
#include <cstdint>

// Problem shape (fixed by the reference): B=4, L=4096, H=1024, F=4096
#define M_TOK  16384
#define H_DIM  1024
#define F_DIM  4096

// Compacted intermediate h (stored TF32-rounded): dense rows [0, Mc)
__device__ float g_h[(size_t)M_TOK * F_DIM];
// Pre-rounded (RNA tf32) weights
__device__ float g_w1[(size_t)H_DIM * F_DIM];
__device__ float g_w2[(size_t)F_DIM * H_DIM];
__device__ int   g_idx[M_TOK];
__device__ int   g_Mc;

#define AS_STRIDE 36    // 32+4 pad: ldmatrix rows (4*row+k)%32 distinct -> conflict-free
#define BS_STRIDE 132   // 128+4 pad: B-frag bank = (4tg+g) -> bijection, conflict-free
#define AS_WORDS  (128 * AS_STRIDE)
#define BS_WORDS  (32 * BS_STRIDE)
#define SMEM_BYTES ((2 * (AS_WORDS + BS_WORDS)) * 4)   // 70656 B

// ---------------------------------------------------------------------------
__device__ __forceinline__ uint32_t f2tf32(float x) {
    uint32_t r;
    asm("cvt.rna.tf32.f32 %0, %1;" : "=r"(r) : "f"(x));
    return r;
}

// Aux 1: zero output (padded rows + 0xAA poison)
__global__ void zero_out_kernel(float4* out, int n4) {
    int i = blockIdx.x * blockDim.x + threadIdx.x;
    if (i < n4) out[i] = make_float4(0.f, 0.f, 0.f, 0.f);
}

// Aux 2: RNA-round both weight matrices into device globals (streaming).
__global__ void round_weights_kernel(const float4* __restrict__ w1,
                                     const float4* __restrict__ w2) {
    const int n1 = H_DIM * F_DIM / 4;
    const int n2 = F_DIM * H_DIM / 4;
    for (int i = blockIdx.x * blockDim.x + threadIdx.x; i < n1 + n2;
         i += gridDim.x * blockDim.x) {
        float4 v = (i < n1) ? w1[i] : w2[i - n1];
        uint4 u;
        u.x = f2tf32(v.x); u.y = f2tf32(v.y);
        u.z = f2tf32(v.z); u.w = f2tf32(v.w);
        if (i < n1) ((uint4*)g_w1)[i] = u;
        else        ((uint4*)g_w2)[i - n1] = u;
    }
}

// Aux 3: order-preserving compaction of non-padded token indices.
__global__ __launch_bounds__(1024) void compact_kernel(const int* __restrict__ padding) {
    __shared__ int warp_tot[32];
    const int t    = threadIdx.x;
    const int lane = t & 31;
    const int w    = t >> 5;

    int flags = 0, cnt = 0;
    const int base = t * 16;
#pragma unroll
    for (int i = 0; i < 16; ++i) {
        int f = (padding[base + i] == 0);
        flags |= f << i;
        cnt += f;
    }
    int inc = cnt;
#pragma unroll
    for (int d = 1; d < 32; d <<= 1) {
        int v = __shfl_up_sync(0xFFFFFFFFu, inc, d);
        if (lane >= d) inc += v;
    }
    if (lane == 31) warp_tot[w] = inc;
    __syncthreads();
    if (w == 0) {
        int v = warp_tot[lane];
        int s = v;
#pragma unroll
        for (int d = 1; d < 32; d <<= 1) {
            int u = __shfl_up_sync(0xFFFFFFFFu, s, d);
            if (lane >= d) s += u;
        }
        warp_tot[lane] = s - v;
        if (lane == 31) g_Mc = s;
    }
    __syncthreads();
    int off = warp_tot[w] + (inc - cnt);
#pragma unroll
    for (int i = 0; i < 16; ++i)
        if ((flags >> i) & 1) g_idx[off++] = base + i;
}

// ---------------------------------------------------------------------------
__device__ __forceinline__ void mma_tf32(float* c, const uint32_t* a, const uint32_t* b) {
    asm volatile(
        "mma.sync.aligned.m16n8k8.row.col.f32.tf32.tf32.f32 "
        "{%0,%1,%2,%3}, {%4,%5,%6,%7}, {%8,%9}, {%0,%1,%2,%3};"
        : "+f"(c[0]), "+f"(c[1]), "+f"(c[2]), "+f"(c[3])
        : "r"(a[0]), "r"(a[1]), "r"(a[2]), "r"(a[3]), "r"(b[0]), "r"(b[1]));
}
__device__ __forceinline__ void ldsm_x4(uint32_t* r, uint32_t saddr) {
    asm volatile(
        "ldmatrix.sync.aligned.m8n8.x4.shared.b16 {%0,%1,%2,%3}, [%4];"
        : "=r"(r[0]), "=r"(r[1]), "=r"(r[2]), "=r"(r[3]) : "r"(saddr));
}
__device__ __forceinline__ void cp_async16(uint32_t smem_dst, const void* gsrc) {
    asm volatile("cp.async.cg.shared.global [%0], [%1], 16;" :: "r"(smem_dst), "l"(gsrc));
}
__device__ __forceinline__ void cp_commit() {
    asm volatile("cp.async.commit_group;");
}
__device__ __forceinline__ void cp_wait0() {
    asm volatile("cp.async.wait_group 0;" ::: "memory");
}

// ---------------------------------------------------------------------------
// Fused compacted GEMM. All smem-resident operands already tf32-rounded:
//   MODE 0: A = x (gathered, LDG+RNA+STS), B = g_w1 (cp.async),
//           C = g_h (stores tf32-rounded relu)
//   MODE 1: A = g_h (cp.async), B = g_w2 (cp.async), C = out (scatter rows)
// 128x128x32 tile, 256 threads, 8 warps (2m x 4n), warp tile 64x32,
// double-buffered, one barrier per k-tile, 2 CTAs/SM.
// A fragments via ldmatrix.x4 (16 scalar LDS -> 1 LDSM per m-tile per k-step).
template <int MODE>
__global__ __launch_bounds__(256, 2)
void ffn_mma_kernel(const float* __restrict__ A,
                    const float* __restrict__ bias,
                    float*       __restrict__ C,
                    int N, int K)
{
    const int Mc = g_Mc;
    const int bm = blockIdx.y * 128;
    if (bm >= Mc) return;

    extern __shared__ uint32_t smem[];
    uint32_t* AsBuf = smem;
    uint32_t* BsBuf = smem + 2 * AS_WORDS;

    const int tid  = threadIdx.x;
    const int wid  = tid >> 5;
    const int lane = tid & 31;
    const int g    = lane >> 2;
    const int tg   = lane & 3;
    const int warp_m = wid & 1;
    const int warp_n = wid >> 1;
    const int bn = blockIdx.x * 128;

    const float* Aeff = (MODE == 1) ? (const float*)g_h : A;
    const float* Bw   = (MODE == 0) ? (const float*)g_w1 : (const float*)g_w2;

    // ---- load mappings (per tile: A 128x32, B 32x128, 4x16B per thread each)
    const int a_row0 = tid >> 3;          // + 32*i
    const int a_kq   = (tid & 7) * 4;
    const int b_k0   = tid >> 5;          // + 8*i
    const int b_nq   = (tid & 31) * 4;

    size_t a_rowoff[4];
#pragma unroll
    for (int i = 0; i < 4; ++i) {
        int r = bm + a_row0 + 32 * i;
        int src;
        if (MODE == 0) src = (r < Mc) ? g_idx[r] : 0;   // clamp: never stored
        else           src = (r < Mc) ? r : 0;
        a_rowoff[i] = (size_t)src * K + a_kq;
    }
    const float* Bptr = Bw + (size_t)b_k0 * N + bn + b_nq;

    const uint32_t as_smem = (uint32_t)__cvta_generic_to_shared(AsBuf);
    const uint32_t b_dst_base = (uint32_t)__cvta_generic_to_shared(BsBuf)
                              + (uint32_t)(b_k0 * BS_STRIDE + b_nq) * 4u;
    const uint32_t a_dst_base = as_smem
                              + (uint32_t)(a_row0 * AS_STRIDE + a_kq) * 4u;

    // ldmatrix per-lane word offsets for the 4 m-tiles (k-step adds 8 words):
    //   mi = lane>>3 selects sub-matrix: row += (mi&1)*8, col += (mi&2)*2
    uint32_t a_frag_off[4];
    {
        const int mi  = lane >> 3;
        const int row_l = (lane & 7) + ((mi & 1) << 3);
        const int col_l = ((mi >> 1) & 1) << 2;
#pragma unroll
        for (int mt = 0; mt < 4; ++mt) {
            const int m0 = warp_m * 64 + mt * 16;
            a_frag_off[mt] = (uint32_t)((m0 + row_l) * AS_STRIDE + col_l);
        }
    }

    float acc[4][4][4];
#pragma unroll
    for (int mt = 0; mt < 4; ++mt)
#pragma unroll
        for (int nt = 0; nt < 4; ++nt)
#pragma unroll
            for (int i = 0; i < 4; ++i) acc[mt][nt][i] = 0.f;

    const int KT = K / 32;
    float4 ra[4];

    // ---- prologue: stage tile 0 into buffer 0
    if (MODE == 0) {
#pragma unroll
        for (int i = 0; i < 4; ++i) ra[i] = *(const float4*)(Aeff + a_rowoff[i]);
    } else {
#pragma unroll
        for (int i = 0; i < 4; ++i)
            cp_async16(a_dst_base + (uint32_t)(32 * i * AS_STRIDE) * 4u,
                       Aeff + a_rowoff[i]);
    }
#pragma unroll
    for (int i = 0; i < 4; ++i)
        cp_async16(b_dst_base + (uint32_t)(8 * i * BS_STRIDE) * 4u,
                   Bptr + (size_t)(8 * i) * N);
    cp_commit();

    if (MODE == 0) {
#pragma unroll
        for (int i = 0; i < 4; ++i) {
            uint4 u;
            u.x = f2tf32(ra[i].x); u.y = f2tf32(ra[i].y);
            u.z = f2tf32(ra[i].z); u.w = f2tf32(ra[i].w);
            *(uint4*)&AsBuf[(a_row0 + 32 * i) * AS_STRIDE + a_kq] = u;
        }
    }
    cp_wait0();
    __syncthreads();

    for (int t = 0; t < KT; ++t) {
        const uint32_t* Bs = BsBuf + (t & 1) * BS_WORDS;
        const uint32_t as_base = as_smem + (uint32_t)((t & 1) * AS_WORDS) * 4u;
        const uint32_t buf_next = ((t + 1) & 1);

        // ---- start async loads for tile t+1
        const bool have_next = (t + 1 < KT);
        if (have_next) {
            const int k0 = (t + 1) * 32;
            if (MODE == 0) {
#pragma unroll
                for (int i = 0; i < 4; ++i)
                    ra[i] = *(const float4*)(Aeff + a_rowoff[i] + k0);
            } else {
#pragma unroll
                for (int i = 0; i < 4; ++i)
                    cp_async16(a_dst_base + (buf_next * AS_WORDS
                               + (uint32_t)(32 * i * AS_STRIDE)) * 4u,
                               Aeff + a_rowoff[i] + k0);
            }
#pragma unroll
            for (int i = 0; i < 4; ++i)
                cp_async16(b_dst_base + (buf_next * BS_WORDS
                           + (uint32_t)(8 * i * BS_STRIDE)) * 4u,
                           Bptr + (size_t)(k0 + 8 * i) * N);
            cp_commit();
        }

        // ---- compute: 4 k-steps x (4 m x 4 n) mmas — LDSM + LDS + MMA
#pragma unroll
        for (int ks = 0; ks < 4; ++ks) {
            const int k = ks * 8;
            uint32_t af[4][4];
#pragma unroll
            for (int mt = 0; mt < 4; ++mt)
                ldsm_x4(af[mt], as_base + (a_frag_off[mt] + (uint32_t)k) * 4u);

            uint32_t bf[4][2];
#pragma unroll
            for (int nt = 0; nt < 4; ++nt) {
                const int n0 = warp_n * 32 + nt * 8 + g;
                bf[nt][0] = Bs[(k + tg)     * BS_STRIDE + n0];
                bf[nt][1] = Bs[(k + tg + 4) * BS_STRIDE + n0];
            }
#pragma unroll
            for (int mt = 0; mt < 4; ++mt)
#pragma unroll
                for (int nt = 0; nt < 4; ++nt)
                    mma_tf32(acc[mt][nt], af[mt], bf[nt]);
        }

        // ---- stage next A (register path, MODE 0 only), seal tile
        if (have_next) {
            if (MODE == 0) {
                uint32_t* Asn = AsBuf + buf_next * AS_WORDS;
#pragma unroll
                for (int i = 0; i < 4; ++i) {
                    uint4 u;
                    u.x = f2tf32(ra[i].x); u.y = f2tf32(ra[i].y);
                    u.z = f2tf32(ra[i].z); u.w = f2tf32(ra[i].w);
                    *(uint4*)&Asn[(a_row0 + 32 * i) * AS_STRIDE + a_kq] = u;
                }
            }
            cp_wait0();
            __syncthreads();
        }
    }

    // ---- epilogue ----
#pragma unroll
    for (int mt = 0; mt < 4; ++mt) {
        const int r0 = bm + warp_m * 64 + mt * 16 + g;
        const int r1 = r0 + 8;

        float* Crow0 = nullptr;
        float* Crow1 = nullptr;
        if (r0 < Mc)
            Crow0 = (MODE == 0) ? (float*)g_h + (size_t)r0 * N
                                : C + (size_t)g_idx[r0] * N;
        if (r1 < Mc)
            Crow1 = (MODE == 0) ? (float*)g_h + (size_t)r1 * N
                                : C + (size_t)g_idx[r1] * N;

#pragma unroll
        for (int nt = 0; nt < 4; ++nt) {
            const int c = bn + warp_n * 32 + nt * 8 + tg * 2;
            const float2 bb = *(const float2*)&bias[c];

            float2 v0, v1;
            v0.x = acc[mt][nt][0] + bb.x;
            v0.y = acc[mt][nt][1] + bb.y;
            v1.x = acc[mt][nt][2] + bb.x;
            v1.y = acc[mt][nt][3] + bb.y;

            if (MODE == 0) {
                // relu + pre-round so GEMM2 consumes h with zero conversion
                v0.x = __uint_as_float(f2tf32(fmaxf(v0.x, 0.f)));
                v0.y = __uint_as_float(f2tf32(fmaxf(v0.y, 0.f)));
                v1.x = __uint_as_float(f2tf32(fmaxf(v1.x, 0.f)));
                v1.y = __uint_as_float(f2tf32(fmaxf(v1.y, 0.f)));
            }
            if (Crow0) *(float2*)&Crow0[c] = v0;
            if (Crow1) *(float2*)&Crow1[c] = v1;
        }
    }
}

extern "C" void kernel_launch(void* const* d_in, const int* in_sizes, int n_in,
                              void* d_out, int out_size)
{
    const float* x       = (const float*)d_in[0];  // [4,4096,1024]
    const int*   padding = (const int*)  d_in[1];  // [4,4096]
    const float* W1      = (const float*)d_in[2];  // [1024,4096]
    const float* b1      = (const float*)d_in[3];  // [4096]
    const float* W2      = (const float*)d_in[4];  // [4096,1024]
    const float* b2      = (const float*)d_in[5];  // [1024]
    float*       out     = (float*)d_out;          // [4,4096,1024]

    cudaFuncSetAttribute(ffn_mma_kernel<0>,
                         cudaFuncAttributeMaxDynamicSharedMemorySize, SMEM_BYTES);
    cudaFuncSetAttribute(ffn_mma_kernel<1>,
                         cudaFuncAttributeMaxDynamicSharedMemorySize, SMEM_BYTES);

    const int n4 = M_TOK * H_DIM / 4;
    zero_out_kernel<<<(n4 + 255) / 256, 256>>>((float4*)out, n4);
    round_weights_kernel<<<1184, 256>>>((const float4*)W1, (const float4*)W2);
    compact_kernel<<<1, 1024>>>(padding);

    dim3 block(256);

    // GEMM1 (gathered): h_c = tf32(relu(x[idx] @ W1 + b1))  [Mc x 4096], K=1024
    dim3 grid1(F_DIM / 128, M_TOK / 128);
    ffn_mma_kernel<0><<<grid1, block, SMEM_BYTES>>>(x, b1, nullptr, F_DIM, H_DIM);

    // GEMM2 (scattered): out[idx] = h_c @ W2 + b2  [Mc x 1024], K=4096
    dim3 grid2(H_DIM / 128, M_TOK / 128);
    ffn_mma_kernel<1><<<grid2, block, SMEM_BYTES>>>(nullptr, b2, out, H_DIM, F_DIM);
}

// round 14
// speedup vs baseline: 1.3313x; 1.0538x over previous
#include <cuda_runtime.h>
#include <cuda_bf16.h>
#include <cstdint>

// Problem shape (fixed by the reference): B=4, L=4096, H=1024, F=4096
#define M_TOK  16384
#define H_DIM  1024
#define F_DIM  4096

// Device-global scratch
__device__ float g_x[(size_t)M_TOK * H_DIM];    // rna(x)
__device__ float g_h[(size_t)M_TOK * F_DIM];    // rna(relu(...)), compacted rows
__device__ float g_w1[(size_t)H_DIM * F_DIM];   // rna(W1) [K][N]
__device__ float g_w2[(size_t)F_DIM * H_DIM];   // rna(W2) [K][N]
__device__ int   g_idx[M_TOK];
__device__ int   g_Mc;

#define AS_STRIDE 36    // 32+4 pad: ldmatrix row banks (4r)%32 distinct -> conflict-free
#define BS_STRIDE 132   // 128+4 pad: B-frag bank = (4tg+g) bijection -> conflict-free
#define AS_WORDS  (128 * AS_STRIDE)             // 4608 words / stage
#define BS_WORDS  (32 * BS_STRIDE)              // 4224 words / stage
#define N_STAGE   3
#define SMEM_BYTES ((N_STAGE * (AS_WORDS + BS_WORDS)) * 4)   // 105984 B

// ---------------------------------------------------------------------------
__device__ __forceinline__ uint32_t f2tf32(float x) {
    uint32_t r;
    asm("cvt.rna.tf32.f32 %0, %1;" : "=r"(r) : "f"(x));
    return r;
}

// Aux 1: zero output (padded rows + 0xAA poison)
__global__ void zero_out_kernel(float4* out, int n4) {
    int i = blockIdx.x * blockDim.x + threadIdx.x;
    if (i < n4) out[i] = make_float4(0.f, 0.f, 0.f, 0.f);
}

// Aux 2: RNA-round both weight matrices into device globals (streaming).
__global__ void round_weights_kernel(const float4* __restrict__ w1,
                                     const float4* __restrict__ w2) {
    const int n1 = H_DIM * F_DIM / 4;
    const int n2 = F_DIM * H_DIM / 4;
    for (int i = blockIdx.x * blockDim.x + threadIdx.x; i < n1 + n2;
         i += gridDim.x * blockDim.x) {
        float4 v = (i < n1) ? w1[i] : w2[i - n1];
        uint4 u;
        u.x = f2tf32(v.x); u.y = f2tf32(v.y);
        u.z = f2tf32(v.z); u.w = f2tf32(v.w);
        if (i < n1) ((uint4*)g_w1)[i] = u;
        else        ((uint4*)g_w2)[i - n1] = u;
    }
}

// Aux 3: RNA-round x into g_x (so GEMM1's A staging is pure cp.async).
__global__ void round_x_kernel(const float4* __restrict__ x) {
    const int n4 = M_TOK * H_DIM / 4;
    for (int i = blockIdx.x * blockDim.x + threadIdx.x; i < n4;
         i += gridDim.x * blockDim.x) {
        float4 v = x[i];
        uint4 u;
        u.x = f2tf32(v.x); u.y = f2tf32(v.y);
        u.z = f2tf32(v.z); u.w = f2tf32(v.w);
        ((uint4*)g_x)[i] = u;
    }
}

// Aux 4: order-preserving compaction of non-padded token indices.
__global__ __launch_bounds__(1024) void compact_kernel(const int* __restrict__ padding) {
    __shared__ int warp_tot[32];
    const int t = threadIdx.x, lane = t & 31, w = t >> 5;
    int flags = 0, cnt = 0;
    const int base = t * 16;
#pragma unroll
    for (int i = 0; i < 16; ++i) {
        int f = (padding[base + i] == 0);
        flags |= f << i; cnt += f;
    }
    int inc = cnt;
#pragma unroll
    for (int d = 1; d < 32; d <<= 1) {
        int v = __shfl_up_sync(0xFFFFFFFFu, inc, d);
        if (lane >= d) inc += v;
    }
    if (lane == 31) warp_tot[w] = inc;
    __syncthreads();
    if (w == 0) {
        int v = warp_tot[lane], s = v;
#pragma unroll
        for (int d = 1; d < 32; d <<= 1) {
            int u = __shfl_up_sync(0xFFFFFFFFu, s, d);
            if (lane >= d) s += u;
        }
        warp_tot[lane] = s - v;
        if (lane == 31) g_Mc = s;
    }
    __syncthreads();
    int off = warp_tot[w] + (inc - cnt);
#pragma unroll
    for (int i = 0; i < 16; ++i)
        if ((flags >> i) & 1) g_idx[off++] = base + i;
}

// ---------------------------------------------------------------------------
__device__ __forceinline__ void mma_tf32(float* c, const uint32_t* a, const uint32_t* b) {
    asm volatile(
        "mma.sync.aligned.m16n8k8.row.col.f32.tf32.tf32.f32 "
        "{%0,%1,%2,%3}, {%4,%5,%6,%7}, {%8,%9}, {%0,%1,%2,%3};"
        : "+f"(c[0]), "+f"(c[1]), "+f"(c[2]), "+f"(c[3])
        : "r"(a[0]), "r"(a[1]), "r"(a[2]), "r"(a[3]), "r"(b[0]), "r"(b[1]));
}
__device__ __forceinline__ void ldsm_x4(uint32_t* r, uint32_t saddr) {
    asm volatile(
        "ldmatrix.sync.aligned.m8n8.x4.shared.b16 {%0,%1,%2,%3}, [%4];"
        : "=r"(r[0]), "=r"(r[1]), "=r"(r[2]), "=r"(r[3]) : "r"(saddr));
}
__device__ __forceinline__ void cp_async16(uint32_t smem_dst, const void* gsrc) {
    asm volatile("cp.async.cg.shared.global [%0], [%1], 16;" :: "r"(smem_dst), "l"(gsrc));
}
__device__ __forceinline__ void cp_commit() { asm volatile("cp.async.commit_group;"); }
__device__ __forceinline__ void cp_wait1()  { asm volatile("cp.async.wait_group 1;" ::: "memory"); }

// ---------------------------------------------------------------------------
// Fused compacted GEMM, all operands pre-rounded (RNA tf32), pure cp.async
// staging, 3-stage pipeline, one barrier per k-tile, 2 CTAs/SM.
//   MODE 0: A = g_x rows gathered via g_idx, B = g_w1, epi relu+rna -> g_h
//   MODE 1: A = g_h dense,                   B = g_w2, epi scatter  -> out
// 128x128x32 tile, 256 threads, 8 warps (2m x 4n), warp tile 64x32.
// A fragments via ldmatrix.x4; B fragments via scalar LDS.
template <int MODE>
__global__ __launch_bounds__(256, 2)
void ffn_mma_kernel(const float* __restrict__ bias,
                    float*       __restrict__ C,
                    int N, int K)
{
    const int Mc = g_Mc;
    const int bm = blockIdx.y * 128;
    if (bm >= Mc) return;

    extern __shared__ uint32_t smem[];
    uint32_t* AsBuf = smem;                         // N_STAGE x AS_WORDS
    uint32_t* BsBuf = smem + N_STAGE * AS_WORDS;    // N_STAGE x BS_WORDS

    const int tid  = threadIdx.x;
    const int wid  = tid >> 5;
    const int lane = tid & 31;
    const int g    = lane >> 2;
    const int tg   = lane & 3;
    const int warp_m = wid & 1;
    const int warp_n = wid >> 1;
    const int bn = blockIdx.x * 128;

    const float* Aeff = (MODE == 1) ? (const float*)g_h : (const float*)g_x;
    const float* Bw   = (MODE == 0) ? (const float*)g_w1 : (const float*)g_w2;

    // ---- staging maps (per tile: A 128x32, B 32x128, 4x16B per thread each)
    const int a_row0 = tid >> 3;          // + 32*i
    const int a_kq   = (tid & 7) * 4;
    const int b_k0   = tid >> 5;          // + 8*i
    const int b_nq   = (tid & 31) * 4;

    size_t a_rowoff[4];
#pragma unroll
    for (int i = 0; i < 4; ++i) {
        int r = bm + a_row0 + 32 * i;
        int src;
        if (MODE == 0) src = (r < Mc) ? g_idx[r] : 0;   // clamp: never stored
        else           src = (r < Mc) ? r : 0;
        a_rowoff[i] = (size_t)src * K + a_kq;
    }
    const float* Bptr = Bw + (size_t)b_k0 * N + bn + b_nq;

    const uint32_t as_smem = (uint32_t)__cvta_generic_to_shared(AsBuf);
    const uint32_t bs_smem = (uint32_t)__cvta_generic_to_shared(BsBuf);
    const uint32_t a_dst   = as_smem + (uint32_t)(a_row0 * AS_STRIDE + a_kq) * 4u;
    const uint32_t b_dst   = bs_smem + (uint32_t)(b_k0 * BS_STRIDE + b_nq) * 4u;

    // stage k-chunk c into pipeline stage s
    auto stage = [&](int c, int s) {
        const uint32_t ao = (uint32_t)(s * AS_WORDS) * 4u;
        const uint32_t bo = (uint32_t)(s * BS_WORDS) * 4u;
        const int k0 = c * 32;
#pragma unroll
        for (int i = 0; i < 4; ++i)
            cp_async16(a_dst + ao + (uint32_t)(32 * i * AS_STRIDE) * 4u,
                       Aeff + a_rowoff[i] + k0);
#pragma unroll
        for (int i = 0; i < 4; ++i)
            cp_async16(b_dst + bo + (uint32_t)(8 * i * BS_STRIDE) * 4u,
                       Bptr + (size_t)(k0 + 8 * i) * N);
    };

    // ldmatrix per-lane word offsets for the 4 m-tiles (k-step adds 8 words)
    uint32_t a_frag_off[4];
    {
        const int mi    = lane >> 3;
        const int row_l = (lane & 7) + ((mi & 1) << 3);
        const int col_l = ((mi >> 1) & 1) << 2;
#pragma unroll
        for (int mt = 0; mt < 4; ++mt) {
            const int m0 = warp_m * 64 + mt * 16;
            a_frag_off[mt] = (uint32_t)((m0 + row_l) * AS_STRIDE + col_l);
        }
    }

    float acc[4][4][4];
#pragma unroll
    for (int mt = 0; mt < 4; ++mt)
#pragma unroll
        for (int nt = 0; nt < 4; ++nt)
#pragma unroll
            for (int i = 0; i < 4; ++i) acc[mt][nt][i] = 0.f;

    const int KT = K / 32;

    // ---- prologue: fill stages 0 and 1
    stage(0, 0); cp_commit();
    stage(1, 1); cp_commit();
    cp_wait1();                 // stage 0 complete
    __syncthreads();

    int cur = 0;
    for (int t = 0; t < KT; ++t) {
        // ---- issue fill for chunk t+2 (into the stage freed 2 barriers ago);
        //      commit every iteration to keep positional group accounting.
        if (t + 2 < KT) {
            int s = cur + 2; if (s >= N_STAGE) s -= N_STAGE;
            stage(t + 2, s);
        }
        cp_commit();

        // ---- compute chunk t from stage cur: LDSM-A + LDS-B + 64 MMA
        const uint32_t* Bs = BsBuf + cur * BS_WORDS;
        const uint32_t as_base = as_smem + (uint32_t)(cur * AS_WORDS) * 4u;
#pragma unroll
        for (int ks = 0; ks < 4; ++ks) {
            const int k = ks * 8;
            uint32_t af[4][4];
#pragma unroll
            for (int mt = 0; mt < 4; ++mt)
                ldsm_x4(af[mt], as_base + (a_frag_off[mt] + (uint32_t)k) * 4u);

            uint32_t bf[4][2];
#pragma unroll
            for (int nt = 0; nt < 4; ++nt) {
                const int n0 = warp_n * 32 + nt * 8 + g;
                bf[nt][0] = Bs[(k + tg)     * BS_STRIDE + n0];
                bf[nt][1] = Bs[(k + tg + 4) * BS_STRIDE + n0];
            }
#pragma unroll
            for (int mt = 0; mt < 4; ++mt)
#pragma unroll
                for (int nt = 0; nt < 4; ++nt)
                    mma_tf32(acc[mt][nt], af[mt], bf[nt]);
        }

        // ---- all but the most recent group complete => stage t+1 ready
        cp_wait1();
        __syncthreads();
        ++cur; if (cur == N_STAGE) cur = 0;
    }

    // ---- epilogue ----
#pragma unroll
    for (int mt = 0; mt < 4; ++mt) {
        const int r0 = bm + warp_m * 64 + mt * 16 + g;
        const int r1 = r0 + 8;

        float* Crow0 = nullptr;
        float* Crow1 = nullptr;
        if (r0 < Mc)
            Crow0 = (MODE == 0) ? (float*)g_h + (size_t)r0 * N
                                : C + (size_t)g_idx[r0] * N;
        if (r1 < Mc)
            Crow1 = (MODE == 0) ? (float*)g_h + (size_t)r1 * N
                                : C + (size_t)g_idx[r1] * N;

#pragma unroll
        for (int nt = 0; nt < 4; ++nt) {
            const int c = bn + warp_n * 32 + nt * 8 + tg * 2;
            const float2 bb = *(const float2*)&bias[c];

            float2 v0, v1;
            v0.x = acc[mt][nt][0] + bb.x;
            v0.y = acc[mt][nt][1] + bb.y;
            v1.x = acc[mt][nt][2] + bb.x;
            v1.y = acc[mt][nt][3] + bb.y;

            if (MODE == 0) {
                // relu + pre-round so GEMM2 consumes h with zero conversion
                v0.x = __uint_as_float(f2tf32(fmaxf(v0.x, 0.f)));
                v0.y = __uint_as_float(f2tf32(fmaxf(v0.y, 0.f)));
                v1.x = __uint_as_float(f2tf32(fmaxf(v1.x, 0.f)));
                v1.y = __uint_as_float(f2tf32(fmaxf(v1.y, 0.f)));
            }
            if (Crow0) *(float2*)&Crow0[c] = v0;
            if (Crow1) *(float2*)&Crow1[c] = v1;
        }
    }
}

extern "C" void kernel_launch(void* const* d_in, const int* in_sizes, int n_in,
                              void* d_out, int out_size)
{
    const float* x       = (const float*)d_in[0];  // [4,4096,1024]
    const int*   padding = (const int*)  d_in[1];  // [4,4096]
    const float* W1      = (const float*)d_in[2];  // [1024,4096]
    const float* b1      = (const float*)d_in[3];  // [4096]
    const float* W2      = (const float*)d_in[4];  // [4096,1024]
    const float* b2      = (const float*)d_in[5];  // [1024]
    float*       out     = (float*)d_out;          // [4,4096,1024]

    cudaFuncSetAttribute(ffn_mma_kernel<0>,
                         cudaFuncAttributeMaxDynamicSharedMemorySize, SMEM_BYTES);
    cudaFuncSetAttribute(ffn_mma_kernel<1>,
                         cudaFuncAttributeMaxDynamicSharedMemorySize, SMEM_BYTES);

    const int n4 = M_TOK * H_DIM / 4;
    zero_out_kernel<<<(n4 + 255) / 256, 256>>>((float4*)out, n4);
    round_weights_kernel<<<1184, 256>>>((const float4*)W1, (const float4*)W2);
    round_x_kernel<<<1184, 256>>>((const float4*)x);
    compact_kernel<<<1, 1024>>>(padding);

    dim3 block(256);

    // GEMM1 (gathered): h_c = tf32(relu(x[idx] @ W1 + b1))  [Mc x 4096], K=1024
    dim3 grid1(F_DIM / 128, M_TOK / 128);
    ffn_mma_kernel<0><<<grid1, block, SMEM_BYTES>>>(b1, nullptr, F_DIM, H_DIM);

    // GEMM2 (scattered): out[idx] = h_c @ W2 + b2  [Mc x 1024], K=4096
    dim3 grid2(H_DIM / 128, M_TOK / 128);
    ffn_mma_kernel<1><<<grid2, block, SMEM_BYTES>>>(b2, out, H_DIM, F_DIM);
}